// round 15
// baseline (speedup 1.0000x reference)
#include <cuda_runtime.h>

#define N_NODES 100000
#define N_EDGES 3200000
#define HID 32
#define NCONV 16
#define NGRP (N_NODES / 8)        // 12500 node-groups (8 nodes/warp)

#define EM1 1.7182818284f         // e - 1
#define SCALE_HID (EM1 / 255.0f)  // dequant scale for hidden layers
#define KOUT (255.0f / EM1)       // quant gain for hidden layers

// ---- device scratch (static globals; zero-initialized at load) ----
__device__ int   g_deg[N_NODES];
__device__ int   g_cursor[N_NODES];
__device__ int   g_rowptr[N_NODES + 1];
__device__ float g_invdeg[N_NODES];
__device__ int   g_csr[N_EDGES];
__device__ __align__(16) unsigned char g_qbufA[N_NODES * HID];
__device__ __align__(16) unsigned char g_qbufB[N_NODES * HID];
__device__ __align__(16) float g_colsum[(NCONV + 1) * HID];
__device__ float g_zexp[N_NODES];
__device__ float g_S[1];

// ---------------------------------------------------------------------------
// per-block dtype detect: if edge_index is int64 (LE), odd 32-bit words are 0.
__device__ __forceinline__ bool detect_is64(const void* ei) {
    __shared__ int s_any;
    if (threadIdx.x == 0) s_any = 0;
    __syncthreads();
    unsigned e = (threadIdx.x * 9973u + blockIdx.x * 131u) % N_EDGES;
    unsigned w = ((const unsigned*)ei)[2 * (size_t)e + 1];
    if (w != 0u) atomicOr(&s_any, 1);
    __syncthreads();
    return s_any == 0;
}

__device__ __forceinline__ int load_edge(const void* p, long long idx, bool is64) {
    if (is64) return (int)((const long long*)p)[idx];
    return ((const int*)p)[idx];
}

__global__ void hist_kernel(const void* __restrict__ ei) {
    bool is64 = detect_is64(ei);
    int i = blockIdx.x * blockDim.x + threadIdx.x;
    if (i < N_EDGES) {
        int d = load_edge(ei, (long long)N_EDGES + i, is64);
        if ((unsigned)d < N_NODES) atomicAdd(&g_deg[d], 1);
    }
}

// single-block scan: deg -> rowptr (exclusive) + invdeg; re-zero deg;
// cursor := rowptr (fill uses it as the absolute write cursor); init colsum/S.
__global__ void scan_kernel() {
    __shared__ int ws[32];
    __shared__ int s_carry;
    int t = threadIdx.x, lane = t & 31, w = t >> 5;
    if (t == 0) s_carry = 0;
    if (t < (NCONV + 1) * HID) g_colsum[t] = (t < HID) ? 1.0f : 0.0f;
    if (t == 0) g_S[0] = 0.0f;
    __syncthreads();
    int4* deg4 = (int4*)g_deg;
    int4* cur4 = (int4*)g_cursor;
    const int NI4 = N_NODES / 4;             // 25000 (exact)
    for (int c = 0; c < (NI4 + 1023) / 1024; ++c) {
        int i4 = c * 1024 + t;
        int4 d = (i4 < NI4) ? deg4[i4] : make_int4(0, 0, 0, 0);
        int tsum = d.x + d.y + d.z + d.w;
        int v = tsum;
#pragma unroll
        for (int o = 1; o < 32; o <<= 1) {
            int u = __shfl_up_sync(0xffffffffu, v, o);
            if (lane >= o) v += u;
        }
        if (lane == 31) ws[w] = v;
        __syncthreads();
        if (w == 0) {
            int s = ws[lane];
#pragma unroll
            for (int o = 1; o < 32; o <<= 1) {
                int u = __shfl_up_sync(0xffffffffu, s, o);
                if (lane >= o) s += u;
            }
            ws[lane] = s;
        }
        __syncthreads();
        int excl = s_carry + (w ? ws[w - 1] : 0) + v - tsum;
        if (i4 < NI4) {
            int base = i4 * 4;
            int4 rp;
            rp.x = excl; rp.y = excl + d.x; rp.z = rp.y + d.y; rp.w = rp.z + d.z;
            *(int4*)&g_rowptr[base] = rp;
            cur4[i4] = rp;                      // cursor starts at row base
            float4 iv;
            iv.x = 1.0f / (float)max(d.x, 1);
            iv.y = 1.0f / (float)max(d.y, 1);
            iv.z = 1.0f / (float)max(d.z, 1);
            iv.w = 1.0f / (float)max(d.w, 1);
            *(float4*)&g_invdeg[base] = iv;
            deg4[i4] = make_int4(0, 0, 0, 0);
        }
        __syncthreads();
        if (t == 0) s_carry += ws[31];
        __syncthreads();
    }
    if (t == 0) g_rowptr[N_NODES] = s_carry;
}

__global__ void fill_kernel(const void* __restrict__ ei) {
    bool is64 = detect_is64(ei);
    int i = blockIdx.x * blockDim.x + threadIdx.x;
    if (i < N_EDGES) {
        int s = load_edge(ei, i, is64);
        int d = load_edge(ei, (long long)N_EDGES + i, is64);
        if ((unsigned)d >= N_NODES || (unsigned)s >= N_NODES) return;
        int p = atomicAdd(&g_cursor[d], 1);   // absolute slot
        g_csr[p] = s;
    }
}

// ---------------------------------------------------------------------------
// proj_in: x[N,4] -> inner-softmax(avg@A_in + x@B_in) [N,32] quantized q=p*255.
__global__ void __launch_bounds__(256) proj_kernel(
    const float* __restrict__ x, const float* __restrict__ Ain,
    const float* __restrict__ Bin, unsigned char* __restrict__ out) {
    __shared__ unsigned char stg[8][HID];
    int lane = threadIdx.x & 31, wid = threadIdx.x >> 5;
    int n = blockIdx.x * 8 + wid;
    if (n >= N_NODES) return;
    int beg = g_rowptr[n], end = g_rowptr[n + 1];
    int gb = lane >> 2, ft = lane & 3;
    float sum = 0.0f;
    for (int base = beg; base < end; base += 8) {
        int j = base + gb;
        if (j < end) {
            int s = __ldg(&g_csr[j]);
            sum += __ldg(&x[s * 4 + ft]);
        }
    }
    sum += __shfl_xor_sync(0xffffffffu, sum, 4);
    sum += __shfl_xor_sync(0xffffffffu, sum, 8);
    sum += __shfl_xor_sync(0xffffffffu, sum, 16);
    float invd = g_invdeg[n];
    float a0 = __shfl_sync(0xffffffffu, sum, 0) * invd;
    float a1 = __shfl_sync(0xffffffffu, sum, 1) * invd;
    float a2 = __shfl_sync(0xffffffffu, sum, 2) * invd;
    float a3 = __shfl_sync(0xffffffffu, sum, 3) * invd;
    float4 xv = *(const float4*)&x[n * 4];
    float acc = a0 * __ldg(&Ain[lane])      + a1 * __ldg(&Ain[32 + lane])
              + a2 * __ldg(&Ain[64 + lane]) + a3 * __ldg(&Ain[96 + lane])
              + xv.x * __ldg(&Bin[lane])      + xv.y * __ldg(&Bin[32 + lane])
              + xv.z * __ldg(&Bin[64 + lane]) + xv.w * __ldg(&Bin[96 + lane]);
    float mx = acc;
#pragma unroll
    for (int o = 16; o; o >>= 1) mx = fmaxf(mx, __shfl_xor_sync(0xffffffffu, mx, o));
    float e = __expf(acc - mx);
    float ss = e;
#pragma unroll
    for (int o = 16; o; o >>= 1) ss += __shfl_xor_sync(0xffffffffu, ss, o);
    unsigned q = __float2uint_rn(fminf(e / ss * 255.0f, 255.0f));
    stg[wid][lane] = (unsigned char)q;
    __syncwarp();
    if (lane < 4) {
        uint2 v = *(uint2*)&stg[wid][lane * 8];
        ((uint2*)out)[n * 4 + lane] = v;
    }
}

// ---------------------------------------------------------------------------
// hidden conv layer, int8 storage, MLP-16 gather: 16-edge chunks, indices
// prefetched one chunk ahead, 16 independent LDG.64s in flight per warp.
// Gather loads use __ldcg (L2-only): 3.2MB random working set has ~0% L1 hit,
// so skipping L1 allocation removes fill overhead from the L1tex path.
// (~80 regs -> 3 blocks/SM; proven best structure, R11/R13.)
__global__ void __launch_bounds__(256) conv_kernel(
    const unsigned char* __restrict__ Ein, unsigned char* __restrict__ Eout,
    const float* __restrict__ Wa, const float* __restrict__ Wb,
    const float* __restrict__ cs_in, float* __restrict__ cs_out,
    float in_off, float in_scale) {
    __shared__ __align__(16) float sWa[HID][HID];
    __shared__ __align__(16) float sWb[HID][HID];
    __shared__ __align__(16) float sred[8][HID];
    int tid = threadIdx.x;
    int lane = tid & 31, wid = tid >> 5;
    for (int i = tid; i < HID * HID; i += 256) {
        ((float*)sWa)[i] = __ldg(&Wa[i]);
        ((float*)sWb)[i] = __ldg(&Wb[i]);
    }
    __syncthreads();

    int nid = lane >> 2;         // node slot within warp (0..7)
    int fl  = lane & 3;          // quarter-row: features fl*8 .. fl*8+7
    int nb  = lane & 28;         // node base lane

    float invS[8];
#pragma unroll
    for (int i = 0; i < 8; ++i) invS[i] = 1.0f / cs_in[fl * 8 + i];
    float colacc[8];
#pragma unroll
    for (int i = 0; i < 8; ++i) colacc[i] = 0.0f;

    const uint2* E2 = (const uint2*)Ein;

    for (int q = blockIdx.x * 8 + wid; q < NGRP; q += gridDim.x * 8) {
        int n = q * 8 + nid;
        int beg = g_rowptr[n], end = g_rowptr[n + 1];
        int deg = end - beg;
        int md = deg;
        md = max(md, __shfl_xor_sync(0xffffffffu, md, 4));
        md = max(md, __shfl_xor_sync(0xffffffffu, md, 8));
        md = max(md, __shfl_xor_sync(0xffffffffu, md, 16));

        unsigned sA = 0, sB = 0, sC = 0, sD = 0;   // u16-pair accumulators

        int ic[4];
#pragma unroll
        for (int t4 = 0; t4 < 4; ++t4) {
            int p = beg + t4 * 4 + fl;
            ic[t4] = (t4 * 4 < md && p < end) ? __ldg(&g_csr[p]) : 0;
        }
        for (int base = 0; base < md; base += 16) {
            int nc[4];
#pragma unroll
            for (int t4 = 0; t4 < 4; ++t4) {
                int p = beg + base + 16 + t4 * 4 + fl;
                nc[t4] = (base + 16 + t4 * 4 < md && p < end) ? __ldg(&g_csr[p]) : 0;
            }
            uint2 v[16];
#pragma unroll
            for (int j = 0; j < 16; ++j) {
                int s = __shfl_sync(0xffffffffu, ic[j >> 2], nb + (j & 3));
                bool act = (base + j < deg);
                v[j] = act ? __ldcg(&E2[s * 4 + fl]) : make_uint2(0u, 0u);
            }
#pragma unroll
            for (int j = 0; j < 16; ++j) {
                sA += __byte_perm(v[j].x, 0, 0x4140);  // b0 | b1<<16
                sB += __byte_perm(v[j].x, 0, 0x4342);  // b2 | b3<<16
                sC += __byte_perm(v[j].y, 0, 0x4140);
                sD += __byte_perm(v[j].y, 0, 0x4342);
            }
#pragma unroll
            for (int t4 = 0; t4 < 4; ++t4) ic[t4] = nc[t4];
        }

        float qs[8];
        qs[0] = (float)(sA & 0xFFFF); qs[1] = (float)(sA >> 16);
        qs[2] = (float)(sB & 0xFFFF); qs[3] = (float)(sB >> 16);
        qs[4] = (float)(sC & 0xFFFF); qs[5] = (float)(sC >> 16);
        qs[6] = (float)(sD & 0xFFFF); qs[7] = (float)(sD >> 16);

        float degf = (float)deg;
        float sc = g_invdeg[n];
        uint2 vx = __ldcg(&E2[n * 4 + fl]);
        float avg[8], xd[8];
        xd[0] = (float)(vx.x & 0xFF);         xd[1] = (float)((vx.x >> 8) & 0xFF);
        xd[2] = (float)((vx.x >> 16) & 0xFF); xd[3] = (float)(vx.x >> 24);
        xd[4] = (float)(vx.y & 0xFF);         xd[5] = (float)((vx.y >> 8) & 0xFF);
        xd[6] = (float)((vx.y >> 16) & 0xFF); xd[7] = (float)(vx.y >> 24);
#pragma unroll
        for (int i = 0; i < 8; ++i) {
            avg[i] = (degf * in_off + qs[i] * in_scale) * sc * invS[i];
            xd[i]  = (in_off + xd[i] * in_scale) * invS[i];
        }

        float acc[8];
#pragma unroll
        for (int i = 0; i < 8; ++i) acc[i] = 0.0f;
#pragma unroll
        for (int c = 0; c < 4; ++c) {
            int src = nb + c;
#pragma unroll
            for (int j = 0; j < 8; ++j) {
                float a  = __shfl_sync(0xffffffffu, avg[j], src);
                float xv = __shfl_sync(0xffffffffu, xd[j],  src);
                int k = c * 8 + j;
                float4 wa0 = *(const float4*)&sWa[k][fl * 8];
                float4 wa1 = *(const float4*)&sWa[k][fl * 8 + 4];
                float4 wb0 = *(const float4*)&sWb[k][fl * 8];
                float4 wb1 = *(const float4*)&sWb[k][fl * 8 + 4];
                acc[0] = fmaf(a, wa0.x, acc[0]); acc[1] = fmaf(a, wa0.y, acc[1]);
                acc[2] = fmaf(a, wa0.z, acc[2]); acc[3] = fmaf(a, wa0.w, acc[3]);
                acc[4] = fmaf(a, wa1.x, acc[4]); acc[5] = fmaf(a, wa1.y, acc[5]);
                acc[6] = fmaf(a, wa1.z, acc[6]); acc[7] = fmaf(a, wa1.w, acc[7]);
                acc[0] = fmaf(xv, wb0.x, acc[0]); acc[1] = fmaf(xv, wb0.y, acc[1]);
                acc[2] = fmaf(xv, wb0.z, acc[2]); acc[3] = fmaf(xv, wb0.w, acc[3]);
                acc[4] = fmaf(xv, wb1.x, acc[4]); acc[5] = fmaf(xv, wb1.y, acc[5]);
                acc[6] = fmaf(xv, wb1.z, acc[6]); acc[7] = fmaf(xv, wb1.w, acc[7]);
            }
        }

        // inner softmax over node's 32 features (4 lanes x 8 comps)
        float mx = acc[0];
#pragma unroll
        for (int i = 1; i < 8; ++i) mx = fmaxf(mx, acc[i]);
        mx = fmaxf(mx, __shfl_xor_sync(0xffffffffu, mx, 1));
        mx = fmaxf(mx, __shfl_xor_sync(0xffffffffu, mx, 2));
        float e[8], ss = 0.0f;
#pragma unroll
        for (int i = 0; i < 8; ++i) { e[i] = __expf(acc[i] - mx); ss += e[i]; }
        ss += __shfl_xor_sync(0xffffffffu, ss, 1);
        ss += __shfl_xor_sync(0xffffffffu, ss, 2);
        float r = 1.0f / ss;
        unsigned qv[8];
#pragma unroll
        for (int i = 0; i < 8; ++i) {
            float E = __expf(e[i] * r);                 // in (1, e]
            unsigned qi = __float2uint_rn(fminf((E - 1.0f) * KOUT, 255.0f));
            qv[i] = qi;
            colacc[i] += 1.0f + (float)qi * SCALE_HID;  // dequantized stored value
        }
        uint2 o;
        o.x = qv[0] | (qv[1] << 8) | (qv[2] << 16) | (qv[3] << 24);
        o.y = qv[4] | (qv[5] << 8) | (qv[6] << 16) | (qv[7] << 24);
        ((uint2*)Eout)[n * 4 + fl] = o;
    }

    // column-sum reduction across the 8 node slots (lanes with same fl)
#pragma unroll
    for (int o = 4; o <= 16; o <<= 1) {
#pragma unroll
        for (int i = 0; i < 8; ++i)
            colacc[i] += __shfl_xor_sync(0xffffffffu, colacc[i], o);
    }
    if (lane < 4) {
        float4 c0 = make_float4(colacc[0], colacc[1], colacc[2], colacc[3]);
        float4 c1 = make_float4(colacc[4], colacc[5], colacc[6], colacc[7]);
        *(float4*)&sred[wid][fl * 8]     = c0;
        *(float4*)&sred[wid][fl * 8 + 4] = c1;
    }
    __syncthreads();
    if (wid == 0) {
        float t = sred[0][lane];
#pragma unroll
        for (int i = 1; i < 8; ++i) t += sred[i][lane];
        atomicAdd(&cs_out[lane], t);
    }
}

// ---------------------------------------------------------------------------
// final z: 8 nodes/warp, 4 lanes/node, uint2 loads + register dot.
__global__ void __launch_bounds__(256) out_z_kernel(
    const unsigned char* __restrict__ E, const float* __restrict__ cs,
    const float* __restrict__ Wout, const float* __restrict__ bout) {
    int lane = threadIdx.x & 31, wid = threadIdx.x >> 5;
    int nid = lane >> 2;
    int fl  = lane & 3;
    float w8[8];
#pragma unroll
    for (int i = 0; i < 8; ++i)
        w8[i] = __ldg(&Wout[fl * 8 + i]) / cs[fl * 8 + i];
    float b = __ldg(bout);
    const uint2* E2 = (const uint2*)E;
    float acc = 0.0f;
    for (int q = blockIdx.x * 8 + wid; q < NGRP; q += gridDim.x * 8) {
        int n = q * 8 + nid;
        uint2 vx = __ldg(&E2[n * 4 + fl]);
        float v = 0.0f;
        v += (1.0f + (float)(vx.x & 0xFF)         * SCALE_HID) * w8[0];
        v += (1.0f + (float)((vx.x >> 8) & 0xFF)  * SCALE_HID) * w8[1];
        v += (1.0f + (float)((vx.x >> 16) & 0xFF) * SCALE_HID) * w8[2];
        v += (1.0f + (float)(vx.x >> 24)          * SCALE_HID) * w8[3];
        v += (1.0f + (float)(vx.y & 0xFF)         * SCALE_HID) * w8[4];
        v += (1.0f + (float)((vx.y >> 8) & 0xFF)  * SCALE_HID) * w8[5];
        v += (1.0f + (float)((vx.y >> 16) & 0xFF) * SCALE_HID) * w8[6];
        v += (1.0f + (float)(vx.y >> 24)          * SCALE_HID) * w8[7];
        v += __shfl_xor_sync(0xffffffffu, v, 1);
        v += __shfl_xor_sync(0xffffffffu, v, 2);
        float e = __expf(v + b);
        if (fl == 0) { g_zexp[n] = e; acc += e; }
    }
#pragma unroll
    for (int o = 16; o; o >>= 1) acc += __shfl_xor_sync(0xffffffffu, acc, o);
    __shared__ float sred[8];
    if (lane == 0) sred[wid] = acc;
    __syncthreads();
    if (threadIdx.x == 0) {
        float t = 0.0f;
#pragma unroll
        for (int i = 0; i < 8; ++i) t += sred[i];
        atomicAdd(g_S, t);
    }
}

__global__ void out_norm_kernel(float* __restrict__ out) {
    int i = blockIdx.x * blockDim.x + threadIdx.x;
    if (i < N_NODES) out[i] = g_zexp[i] / g_S[0];
}

// ---------------------------------------------------------------------------
extern "C" void kernel_launch(void* const* d_in, const int* in_sizes, int n_in,
                              void* d_out, int out_size) {
    const float* x     = (const float*)d_in[0];
    const void*  ei    = d_in[1];                    // [2, N_EDGES] int32 or int64
    const float* Ain   = (const float*)d_in[2];
    const float* Bin   = (const float*)d_in[3];
    const float* Aconv = (const float*)d_in[4];      // [16,32,32]
    const float* Bconv = (const float*)d_in[5];
    const float* Wout  = (const float*)d_in[6];
    const float* bout  = (const float*)d_in[7];
    float* out         = (float*)d_out;

    unsigned char *pA, *pB;
    float *pcs;
    cudaGetSymbolAddress((void**)&pA, g_qbufA);
    cudaGetSymbolAddress((void**)&pB, g_qbufB);
    cudaGetSymbolAddress((void**)&pcs, g_colsum);

    hist_kernel<<<(N_EDGES + 255) / 256, 256>>>(ei);
    scan_kernel<<<1, 1024>>>();
    fill_kernel<<<(N_EDGES + 255) / 256, 256>>>(ei);

    proj_kernel<<<(N_NODES + 7) / 8, 256>>>(x, Ain, Bin, pA);

    unsigned char* bi = pA;
    unsigned char* bo = pB;
    for (int l = 0; l < NCONV; ++l) {
        float in_off   = (l == 0) ? 0.0f : 1.0f;
        float in_scale = (l == 0) ? (1.0f / 255.0f) : SCALE_HID;
        conv_kernel<<<444, 256>>>(bi, bo,
                                  Aconv + l * HID * HID, Bconv + l * HID * HID,
                                  pcs + l * HID, pcs + (l + 1) * HID,
                                  in_off, in_scale);
        unsigned char* t = bi; bi = bo; bo = t;
    }

    out_z_kernel<<<444, 256>>>(bi, pcs + NCONV * HID, Wout, bout);
    out_norm_kernel<<<(N_NODES + 255) / 256, 256>>>(out);
}

// round 16
// speedup vs baseline: 1.6072x; 1.6072x over previous
#include <cuda_runtime.h>

#define N_NODES 100000
#define N_EDGES 3200000
#define HID 32
#define NCONV 16
#define NGRP (N_NODES / 8)        // 12500 node-groups (8 nodes/warp)

#define EM1 1.7182818284f         // e - 1
#define SCALE_HID (EM1 / 255.0f)  // dequant scale for hidden layers
#define KOUT (255.0f / EM1)       // quant gain for hidden layers

// ---- device scratch (static globals; zero-initialized at load) ----
__device__ int   g_deg[N_NODES];
__device__ int   g_cursor[N_NODES];
__device__ int   g_rowptr[N_NODES + 1];
__device__ float g_invdeg[N_NODES];
__device__ int   g_csr[N_EDGES];
__device__ __align__(16) unsigned char g_qbufA[N_NODES * HID];
__device__ __align__(16) unsigned char g_qbufB[N_NODES * HID];
__device__ __align__(16) float g_colsum[(NCONV + 1) * HID];
__device__ float g_zexp[N_NODES];
__device__ float g_S[1];

// ---------------------------------------------------------------------------
// per-block dtype detect: if edge_index is int64 (LE), odd 32-bit words are 0.
__device__ __forceinline__ bool detect_is64(const void* ei) {
    __shared__ int s_any;
    if (threadIdx.x == 0) s_any = 0;
    __syncthreads();
    unsigned e = (threadIdx.x * 9973u + blockIdx.x * 131u) % N_EDGES;
    unsigned w = ((const unsigned*)ei)[2 * (size_t)e + 1];
    if (w != 0u) atomicOr(&s_any, 1);
    __syncthreads();
    return s_any == 0;
}

__device__ __forceinline__ int load_edge(const void* p, long long idx, bool is64) {
    if (is64) return (int)((const long long*)p)[idx];
    return ((const int*)p)[idx];
}

__global__ void hist_kernel(const void* __restrict__ ei) {
    bool is64 = detect_is64(ei);
    int i = blockIdx.x * blockDim.x + threadIdx.x;
    if (i < N_EDGES) {
        int d = load_edge(ei, (long long)N_EDGES + i, is64);
        if ((unsigned)d < N_NODES) atomicAdd(&g_deg[d], 1);
    }
}

// single-block scan: deg -> rowptr (exclusive) + invdeg; re-zero deg;
// cursor := rowptr (fill uses it as the absolute write cursor); init colsum/S.
__global__ void scan_kernel() {
    __shared__ int ws[32];
    __shared__ int s_carry;
    int t = threadIdx.x, lane = t & 31, w = t >> 5;
    if (t == 0) s_carry = 0;
    if (t < (NCONV + 1) * HID) g_colsum[t] = (t < HID) ? 1.0f : 0.0f;
    if (t == 0) g_S[0] = 0.0f;
    __syncthreads();
    int4* deg4 = (int4*)g_deg;
    int4* cur4 = (int4*)g_cursor;
    const int NI4 = N_NODES / 4;             // 25000 (exact)
    for (int c = 0; c < (NI4 + 1023) / 1024; ++c) {
        int i4 = c * 1024 + t;
        int4 d = (i4 < NI4) ? deg4[i4] : make_int4(0, 0, 0, 0);
        int tsum = d.x + d.y + d.z + d.w;
        int v = tsum;
#pragma unroll
        for (int o = 1; o < 32; o <<= 1) {
            int u = __shfl_up_sync(0xffffffffu, v, o);
            if (lane >= o) v += u;
        }
        if (lane == 31) ws[w] = v;
        __syncthreads();
        if (w == 0) {
            int s = ws[lane];
#pragma unroll
            for (int o = 1; o < 32; o <<= 1) {
                int u = __shfl_up_sync(0xffffffffu, s, o);
                if (lane >= o) s += u;
            }
            ws[lane] = s;
        }
        __syncthreads();
        int excl = s_carry + (w ? ws[w - 1] : 0) + v - tsum;
        if (i4 < NI4) {
            int base = i4 * 4;
            int4 rp;
            rp.x = excl; rp.y = excl + d.x; rp.z = rp.y + d.y; rp.w = rp.z + d.z;
            *(int4*)&g_rowptr[base] = rp;
            cur4[i4] = rp;                      // cursor starts at row base
            float4 iv;
            iv.x = 1.0f / (float)max(d.x, 1);
            iv.y = 1.0f / (float)max(d.y, 1);
            iv.z = 1.0f / (float)max(d.z, 1);
            iv.w = 1.0f / (float)max(d.w, 1);
            *(float4*)&g_invdeg[base] = iv;
            deg4[i4] = make_int4(0, 0, 0, 0);
        }
        __syncthreads();
        if (t == 0) s_carry += ws[31];
        __syncthreads();
    }
    if (t == 0) g_rowptr[N_NODES] = s_carry;
}

__global__ void fill_kernel(const void* __restrict__ ei) {
    bool is64 = detect_is64(ei);
    int i = blockIdx.x * blockDim.x + threadIdx.x;
    if (i < N_EDGES) {
        int s = load_edge(ei, i, is64);
        int d = load_edge(ei, (long long)N_EDGES + i, is64);
        if ((unsigned)d >= N_NODES || (unsigned)s >= N_NODES) return;
        int p = atomicAdd(&g_cursor[d], 1);   // absolute slot
        g_csr[p] = s;
    }
}

// ---------------------------------------------------------------------------
// proj_in: x[N,4] -> inner-softmax(avg@A_in + x@B_in) [N,32] quantized q=p*255.
__global__ void __launch_bounds__(256) proj_kernel(
    const float* __restrict__ x, const float* __restrict__ Ain,
    const float* __restrict__ Bin, unsigned char* __restrict__ out) {
    __shared__ unsigned char stg[8][HID];
    int lane = threadIdx.x & 31, wid = threadIdx.x >> 5;
    int n = blockIdx.x * 8 + wid;
    if (n >= N_NODES) return;
    int beg = g_rowptr[n], end = g_rowptr[n + 1];
    int gb = lane >> 2, ft = lane & 3;
    float sum = 0.0f;
    for (int base = beg; base < end; base += 8) {
        int j = base + gb;
        if (j < end) {
            int s = __ldg(&g_csr[j]);
            sum += __ldg(&x[s * 4 + ft]);
        }
    }
    sum += __shfl_xor_sync(0xffffffffu, sum, 4);
    sum += __shfl_xor_sync(0xffffffffu, sum, 8);
    sum += __shfl_xor_sync(0xffffffffu, sum, 16);
    float invd = g_invdeg[n];
    float a0 = __shfl_sync(0xffffffffu, sum, 0) * invd;
    float a1 = __shfl_sync(0xffffffffu, sum, 1) * invd;
    float a2 = __shfl_sync(0xffffffffu, sum, 2) * invd;
    float a3 = __shfl_sync(0xffffffffu, sum, 3) * invd;
    float4 xv = *(const float4*)&x[n * 4];
    float acc = a0 * __ldg(&Ain[lane])      + a1 * __ldg(&Ain[32 + lane])
              + a2 * __ldg(&Ain[64 + lane]) + a3 * __ldg(&Ain[96 + lane])
              + xv.x * __ldg(&Bin[lane])      + xv.y * __ldg(&Bin[32 + lane])
              + xv.z * __ldg(&Bin[64 + lane]) + xv.w * __ldg(&Bin[96 + lane]);
    float mx = acc;
#pragma unroll
    for (int o = 16; o; o >>= 1) mx = fmaxf(mx, __shfl_xor_sync(0xffffffffu, mx, o));
    float e = __expf(acc - mx);
    float ss = e;
#pragma unroll
    for (int o = 16; o; o >>= 1) ss += __shfl_xor_sync(0xffffffffu, ss, o);
    unsigned q = __float2uint_rn(fminf(e / ss * 255.0f, 255.0f));
    stg[wid][lane] = (unsigned char)q;
    __syncwarp();
    if (lane < 4) {
        uint2 v = *(uint2*)&stg[wid][lane * 8];
        ((uint2*)out)[n * 4 + lane] = v;
    }
}

// ---------------------------------------------------------------------------
// hidden conv layer, int8 storage, MLP-16 gather: 16-edge chunks, indices
// prefetched one chunk ahead, 16 independent LDG.64s in flight per warp.
// (~80 regs -> 3 blocks/SM; proven best config, R11/R13. __ldg is load-
// bearing: L1 allocation of gather lines gives a material hit fraction.)
__global__ void __launch_bounds__(256) conv_kernel(
    const unsigned char* __restrict__ Ein, unsigned char* __restrict__ Eout,
    const float* __restrict__ Wa, const float* __restrict__ Wb,
    const float* __restrict__ cs_in, float* __restrict__ cs_out,
    float in_off, float in_scale) {
    __shared__ __align__(16) float sWa[HID][HID];
    __shared__ __align__(16) float sWb[HID][HID];
    __shared__ __align__(16) float sred[8][HID];
    int tid = threadIdx.x;
    int lane = tid & 31, wid = tid >> 5;
    for (int i = tid; i < HID * HID; i += 256) {
        ((float*)sWa)[i] = __ldg(&Wa[i]);
        ((float*)sWb)[i] = __ldg(&Wb[i]);
    }
    __syncthreads();

    int nid = lane >> 2;         // node slot within warp (0..7)
    int fl  = lane & 3;          // quarter-row: features fl*8 .. fl*8+7
    int nb  = lane & 28;         // node base lane

    float invS[8];
#pragma unroll
    for (int i = 0; i < 8; ++i) invS[i] = 1.0f / cs_in[fl * 8 + i];
    float colacc[8];
#pragma unroll
    for (int i = 0; i < 8; ++i) colacc[i] = 0.0f;

    const uint2* E2 = (const uint2*)Ein;

    for (int q = blockIdx.x * 8 + wid; q < NGRP; q += gridDim.x * 8) {
        int n = q * 8 + nid;
        int beg = g_rowptr[n], end = g_rowptr[n + 1];
        int deg = end - beg;
        int md = deg;
        md = max(md, __shfl_xor_sync(0xffffffffu, md, 4));
        md = max(md, __shfl_xor_sync(0xffffffffu, md, 8));
        md = max(md, __shfl_xor_sync(0xffffffffu, md, 16));

        unsigned sA = 0, sB = 0, sC = 0, sD = 0;   // u16-pair accumulators

        int ic[4];
#pragma unroll
        for (int t4 = 0; t4 < 4; ++t4) {
            int p = beg + t4 * 4 + fl;
            ic[t4] = (t4 * 4 < md && p < end) ? __ldg(&g_csr[p]) : 0;
        }
        for (int base = 0; base < md; base += 16) {
            int nc[4];
#pragma unroll
            for (int t4 = 0; t4 < 4; ++t4) {
                int p = beg + base + 16 + t4 * 4 + fl;
                nc[t4] = (base + 16 + t4 * 4 < md && p < end) ? __ldg(&g_csr[p]) : 0;
            }
            uint2 v[16];
#pragma unroll
            for (int j = 0; j < 16; ++j) {
                int s = __shfl_sync(0xffffffffu, ic[j >> 2], nb + (j & 3));
                bool act = (base + j < deg);
                v[j] = act ? __ldg(&E2[s * 4 + fl]) : make_uint2(0u, 0u);
            }
#pragma unroll
            for (int j = 0; j < 16; ++j) {
                sA += __byte_perm(v[j].x, 0, 0x4140);  // b0 | b1<<16
                sB += __byte_perm(v[j].x, 0, 0x4342);  // b2 | b3<<16
                sC += __byte_perm(v[j].y, 0, 0x4140);
                sD += __byte_perm(v[j].y, 0, 0x4342);
            }
#pragma unroll
            for (int t4 = 0; t4 < 4; ++t4) ic[t4] = nc[t4];
        }

        float qs[8];
        qs[0] = (float)(sA & 0xFFFF); qs[1] = (float)(sA >> 16);
        qs[2] = (float)(sB & 0xFFFF); qs[3] = (float)(sB >> 16);
        qs[4] = (float)(sC & 0xFFFF); qs[5] = (float)(sC >> 16);
        qs[6] = (float)(sD & 0xFFFF); qs[7] = (float)(sD >> 16);

        float degf = (float)deg;
        float sc = g_invdeg[n];
        uint2 vx = __ldg(&E2[n * 4 + fl]);
        float avg[8], xd[8];
        xd[0] = (float)(vx.x & 0xFF);         xd[1] = (float)((vx.x >> 8) & 0xFF);
        xd[2] = (float)((vx.x >> 16) & 0xFF); xd[3] = (float)(vx.x >> 24);
        xd[4] = (float)(vx.y & 0xFF);         xd[5] = (float)((vx.y >> 8) & 0xFF);
        xd[6] = (float)((vx.y >> 16) & 0xFF); xd[7] = (float)(vx.y >> 24);
#pragma unroll
        for (int i = 0; i < 8; ++i) {
            avg[i] = (degf * in_off + qs[i] * in_scale) * sc * invS[i];
            xd[i]  = (in_off + xd[i] * in_scale) * invS[i];
        }

        float acc[8];
#pragma unroll
        for (int i = 0; i < 8; ++i) acc[i] = 0.0f;
#pragma unroll
        for (int c = 0; c < 4; ++c) {
            int src = nb + c;
#pragma unroll
            for (int j = 0; j < 8; ++j) {
                float a  = __shfl_sync(0xffffffffu, avg[j], src);
                float xv = __shfl_sync(0xffffffffu, xd[j],  src);
                int k = c * 8 + j;
                float4 wa0 = *(const float4*)&sWa[k][fl * 8];
                float4 wa1 = *(const float4*)&sWa[k][fl * 8 + 4];
                float4 wb0 = *(const float4*)&sWb[k][fl * 8];
                float4 wb1 = *(const float4*)&sWb[k][fl * 8 + 4];
                acc[0] = fmaf(a, wa0.x, acc[0]); acc[1] = fmaf(a, wa0.y, acc[1]);
                acc[2] = fmaf(a, wa0.z, acc[2]); acc[3] = fmaf(a, wa0.w, acc[3]);
                acc[4] = fmaf(a, wa1.x, acc[4]); acc[5] = fmaf(a, wa1.y, acc[5]);
                acc[6] = fmaf(a, wa1.z, acc[6]); acc[7] = fmaf(a, wa1.w, acc[7]);
                acc[0] = fmaf(xv, wb0.x, acc[0]); acc[1] = fmaf(xv, wb0.y, acc[1]);
                acc[2] = fmaf(xv, wb0.z, acc[2]); acc[3] = fmaf(xv, wb0.w, acc[3]);
                acc[4] = fmaf(xv, wb1.x, acc[4]); acc[5] = fmaf(xv, wb1.y, acc[5]);
                acc[6] = fmaf(xv, wb1.z, acc[6]); acc[7] = fmaf(xv, wb1.w, acc[7]);
            }
        }

        // inner softmax over node's 32 features (4 lanes x 8 comps)
        float mx = acc[0];
#pragma unroll
        for (int i = 1; i < 8; ++i) mx = fmaxf(mx, acc[i]);
        mx = fmaxf(mx, __shfl_xor_sync(0xffffffffu, mx, 1));
        mx = fmaxf(mx, __shfl_xor_sync(0xffffffffu, mx, 2));
        float e[8], ss = 0.0f;
#pragma unroll
        for (int i = 0; i < 8; ++i) { e[i] = __expf(acc[i] - mx); ss += e[i]; }
        ss += __shfl_xor_sync(0xffffffffu, ss, 1);
        ss += __shfl_xor_sync(0xffffffffu, ss, 2);
        float r = 1.0f / ss;
        unsigned qv[8];
#pragma unroll
        for (int i = 0; i < 8; ++i) {
            float E = __expf(e[i] * r);                 // in (1, e]
            unsigned qi = __float2uint_rn(fminf((E - 1.0f) * KOUT, 255.0f));
            qv[i] = qi;
            colacc[i] += 1.0f + (float)qi * SCALE_HID;  // dequantized stored value
        }
        uint2 o;
        o.x = qv[0] | (qv[1] << 8) | (qv[2] << 16) | (qv[3] << 24);
        o.y = qv[4] | (qv[5] << 8) | (qv[6] << 16) | (qv[7] << 24);
        ((uint2*)Eout)[n * 4 + fl] = o;
    }

    // column-sum reduction across the 8 node slots (lanes with same fl)
#pragma unroll
    for (int o = 4; o <= 16; o <<= 1) {
#pragma unroll
        for (int i = 0; i < 8; ++i)
            colacc[i] += __shfl_xor_sync(0xffffffffu, colacc[i], o);
    }
    if (lane < 4) {
        float4 c0 = make_float4(colacc[0], colacc[1], colacc[2], colacc[3]);
        float4 c1 = make_float4(colacc[4], colacc[5], colacc[6], colacc[7]);
        *(float4*)&sred[wid][fl * 8]     = c0;
        *(float4*)&sred[wid][fl * 8 + 4] = c1;
    }
    __syncthreads();
    if (wid == 0) {
        float t = sred[0][lane];
#pragma unroll
        for (int i = 1; i < 8; ++i) t += sred[i][lane];
        atomicAdd(&cs_out[lane], t);
    }
}

// ---------------------------------------------------------------------------
// final z: 8 nodes/warp, 4 lanes/node, uint2 loads + register dot.
__global__ void __launch_bounds__(256) out_z_kernel(
    const unsigned char* __restrict__ E, const float* __restrict__ cs,
    const float* __restrict__ Wout, const float* __restrict__ bout) {
    int lane = threadIdx.x & 31, wid = threadIdx.x >> 5;
    int nid = lane >> 2;
    int fl  = lane & 3;
    float w8[8];
#pragma unroll
    for (int i = 0; i < 8; ++i)
        w8[i] = __ldg(&Wout[fl * 8 + i]) / cs[fl * 8 + i];
    float b = __ldg(bout);
    const uint2* E2 = (const uint2*)E;
    float acc = 0.0f;
    for (int q = blockIdx.x * 8 + wid; q < NGRP; q += gridDim.x * 8) {
        int n = q * 8 + nid;
        uint2 vx = __ldg(&E2[n * 4 + fl]);
        float v = 0.0f;
        v += (1.0f + (float)(vx.x & 0xFF)         * SCALE_HID) * w8[0];
        v += (1.0f + (float)((vx.x >> 8) & 0xFF)  * SCALE_HID) * w8[1];
        v += (1.0f + (float)((vx.x >> 16) & 0xFF) * SCALE_HID) * w8[2];
        v += (1.0f + (float)(vx.x >> 24)          * SCALE_HID) * w8[3];
        v += (1.0f + (float)(vx.y & 0xFF)         * SCALE_HID) * w8[4];
        v += (1.0f + (float)((vx.y >> 8) & 0xFF)  * SCALE_HID) * w8[5];
        v += (1.0f + (float)((vx.y >> 16) & 0xFF) * SCALE_HID) * w8[6];
        v += (1.0f + (float)(vx.y >> 24)          * SCALE_HID) * w8[7];
        v += __shfl_xor_sync(0xffffffffu, v, 1);
        v += __shfl_xor_sync(0xffffffffu, v, 2);
        float e = __expf(v + b);
        if (fl == 0) { g_zexp[n] = e; acc += e; }
    }
#pragma unroll
    for (int o = 16; o; o >>= 1) acc += __shfl_xor_sync(0xffffffffu, acc, o);
    __shared__ float sred[8];
    if (lane == 0) sred[wid] = acc;
    __syncthreads();
    if (threadIdx.x == 0) {
        float t = 0.0f;
#pragma unroll
        for (int i = 0; i < 8; ++i) t += sred[i];
        atomicAdd(g_S, t);
    }
}

__global__ void out_norm_kernel(float* __restrict__ out) {
    int i = blockIdx.x * blockDim.x + threadIdx.x;
    if (i < N_NODES) out[i] = g_zexp[i] / g_S[0];
}

// ---------------------------------------------------------------------------
extern "C" void kernel_launch(void* const* d_in, const int* in_sizes, int n_in,
                              void* d_out, int out_size) {
    const float* x     = (const float*)d_in[0];
    const void*  ei    = d_in[1];                    // [2, N_EDGES] int32 or int64
    const float* Ain   = (const float*)d_in[2];
    const float* Bin   = (const float*)d_in[3];
    const float* Aconv = (const float*)d_in[4];      // [16,32,32]
    const float* Bconv = (const float*)d_in[5];
    const float* Wout  = (const float*)d_in[6];
    const float* bout  = (const float*)d_in[7];
    float* out         = (float*)d_out;

    unsigned char *pA, *pB;
    float *pcs;
    cudaGetSymbolAddress((void**)&pA, g_qbufA);
    cudaGetSymbolAddress((void**)&pB, g_qbufB);
    cudaGetSymbolAddress((void**)&pcs, g_colsum);

    hist_kernel<<<(N_EDGES + 255) / 256, 256>>>(ei);
    scan_kernel<<<1, 1024>>>();
    fill_kernel<<<(N_EDGES + 255) / 256, 256>>>(ei);

    proj_kernel<<<(N_NODES + 7) / 8, 256>>>(x, Ain, Bin, pA);

    unsigned char* bi = pA;
    unsigned char* bo = pB;
    for (int l = 0; l < NCONV; ++l) {
        float in_off   = (l == 0) ? 0.0f : 1.0f;
        float in_scale = (l == 0) ? (1.0f / 255.0f) : SCALE_HID;
        conv_kernel<<<444, 256>>>(bi, bo,
                                  Aconv + l * HID * HID, Bconv + l * HID * HID,
                                  pcs + l * HID, pcs + (l + 1) * HID,
                                  in_off, in_scale);
        unsigned char* t = bi; bi = bo; bo = t;
    }

    out_z_kernel<<<444, 256>>>(bi, pcs + NCONV * HID, Wout, bout);
    out_norm_kernel<<<(N_NODES + 255) / 256, 256>>>(out);
}

// round 17
// speedup vs baseline: 1.6227x; 1.0097x over previous
#include <cuda_runtime.h>

#define N_NODES 100000
#define N_EDGES 3200000
#define HID 32
#define NCONV 16
#define NGRP (N_NODES / 8)        // 12500 node-groups (8 nodes/warp)

#define EM1 1.7182818284f         // e - 1
#define SCALE_HID (EM1 / 255.0f)  // dequant scale for hidden layers
#define KOUT (255.0f / EM1)       // quant gain for hidden layers

// ---- device scratch (static globals; zero-initialized at load) ----
__device__ int   g_deg[N_NODES];
__device__ int   g_cursor[N_NODES];
__device__ int   g_rowptr[N_NODES + 1];
__device__ float g_invdeg[N_NODES];
__device__ int   g_csr[N_EDGES];
__device__ __align__(16) unsigned char g_qbufA[N_NODES * HID];
__device__ __align__(16) unsigned char g_qbufB[N_NODES * HID];
__device__ __align__(16) float g_colsum[(NCONV + 1) * HID];
__device__ float g_zexp[N_NODES];
__device__ float g_S[1];

// ---------------------------------------------------------------------------
// per-block dtype detect: if edge_index is int64 (LE), odd 32-bit words are 0.
__device__ __forceinline__ bool detect_is64(const void* ei) {
    __shared__ int s_any;
    if (threadIdx.x == 0) s_any = 0;
    __syncthreads();
    unsigned e = (threadIdx.x * 9973u + blockIdx.x * 131u) % N_EDGES;
    unsigned w = ((const unsigned*)ei)[2 * (size_t)e + 1];
    if (w != 0u) atomicOr(&s_any, 1);
    __syncthreads();
    return s_any == 0;
}

__device__ __forceinline__ int load_edge(const void* p, long long idx, bool is64) {
    if (is64) return (int)((const long long*)p)[idx];
    return ((const int*)p)[idx];
}

__global__ void hist_kernel(const void* __restrict__ ei) {
    bool is64 = detect_is64(ei);
    int i = blockIdx.x * blockDim.x + threadIdx.x;
    if (i < N_EDGES) {
        int d = load_edge(ei, (long long)N_EDGES + i, is64);
        if ((unsigned)d < N_NODES) atomicAdd(&g_deg[d], 1);
    }
}

// single-block scan: deg -> rowptr (exclusive) + invdeg; re-zero deg;
// cursor := rowptr (fill uses it as the absolute write cursor); init colsum/S.
__global__ void scan_kernel() {
    __shared__ int ws[32];
    __shared__ int s_carry;
    int t = threadIdx.x, lane = t & 31, w = t >> 5;
    if (t == 0) s_carry = 0;
    if (t < (NCONV + 1) * HID) g_colsum[t] = (t < HID) ? 1.0f : 0.0f;
    if (t == 0) g_S[0] = 0.0f;
    __syncthreads();
    int4* deg4 = (int4*)g_deg;
    int4* cur4 = (int4*)g_cursor;
    const int NI4 = N_NODES / 4;             // 25000 (exact)
    for (int c = 0; c < (NI4 + 1023) / 1024; ++c) {
        int i4 = c * 1024 + t;
        int4 d = (i4 < NI4) ? deg4[i4] : make_int4(0, 0, 0, 0);
        int tsum = d.x + d.y + d.z + d.w;
        int v = tsum;
#pragma unroll
        for (int o = 1; o < 32; o <<= 1) {
            int u = __shfl_up_sync(0xffffffffu, v, o);
            if (lane >= o) v += u;
        }
        if (lane == 31) ws[w] = v;
        __syncthreads();
        if (w == 0) {
            int s = ws[lane];
#pragma unroll
            for (int o = 1; o < 32; o <<= 1) {
                int u = __shfl_up_sync(0xffffffffu, s, o);
                if (lane >= o) s += u;
            }
            ws[lane] = s;
        }
        __syncthreads();
        int excl = s_carry + (w ? ws[w - 1] : 0) + v - tsum;
        if (i4 < NI4) {
            int base = i4 * 4;
            int4 rp;
            rp.x = excl; rp.y = excl + d.x; rp.z = rp.y + d.y; rp.w = rp.z + d.z;
            *(int4*)&g_rowptr[base] = rp;
            cur4[i4] = rp;                      // cursor starts at row base
            float4 iv;
            iv.x = 1.0f / (float)max(d.x, 1);
            iv.y = 1.0f / (float)max(d.y, 1);
            iv.z = 1.0f / (float)max(d.z, 1);
            iv.w = 1.0f / (float)max(d.w, 1);
            *(float4*)&g_invdeg[base] = iv;
            deg4[i4] = make_int4(0, 0, 0, 0);
        }
        __syncthreads();
        if (t == 0) s_carry += ws[31];
        __syncthreads();
    }
    if (t == 0) g_rowptr[N_NODES] = s_carry;
}

__global__ void fill_kernel(const void* __restrict__ ei) {
    bool is64 = detect_is64(ei);
    int i = blockIdx.x * blockDim.x + threadIdx.x;
    if (i < N_EDGES) {
        int s = load_edge(ei, i, is64);
        int d = load_edge(ei, (long long)N_EDGES + i, is64);
        if ((unsigned)d >= N_NODES || (unsigned)s >= N_NODES) return;
        int p = atomicAdd(&g_cursor[d], 1);   // absolute slot
        g_csr[p] = s;
    }
}

// ---------------------------------------------------------------------------
// proj_in: x[N,4] -> inner-softmax(avg@A_in + x@B_in) [N,32] quantized q=p*255.
// Logits are O(1)-bounded -> softmax without max-subtraction is safe.
__global__ void __launch_bounds__(256) proj_kernel(
    const float* __restrict__ x, const float* __restrict__ Ain,
    const float* __restrict__ Bin, unsigned char* __restrict__ out) {
    __shared__ unsigned char stg[8][HID];
    int lane = threadIdx.x & 31, wid = threadIdx.x >> 5;
    int n = blockIdx.x * 8 + wid;
    if (n >= N_NODES) return;
    int beg = g_rowptr[n], end = g_rowptr[n + 1];
    int gb = lane >> 2, ft = lane & 3;
    float sum = 0.0f;
    for (int base = beg; base < end; base += 8) {
        int j = base + gb;
        if (j < end) {
            int s = __ldg(&g_csr[j]);
            sum += __ldg(&x[s * 4 + ft]);
        }
    }
    sum += __shfl_xor_sync(0xffffffffu, sum, 4);
    sum += __shfl_xor_sync(0xffffffffu, sum, 8);
    sum += __shfl_xor_sync(0xffffffffu, sum, 16);
    float invd = g_invdeg[n];
    float a0 = __shfl_sync(0xffffffffu, sum, 0) * invd;
    float a1 = __shfl_sync(0xffffffffu, sum, 1) * invd;
    float a2 = __shfl_sync(0xffffffffu, sum, 2) * invd;
    float a3 = __shfl_sync(0xffffffffu, sum, 3) * invd;
    float4 xv = *(const float4*)&x[n * 4];
    float acc = a0 * __ldg(&Ain[lane])      + a1 * __ldg(&Ain[32 + lane])
              + a2 * __ldg(&Ain[64 + lane]) + a3 * __ldg(&Ain[96 + lane])
              + xv.x * __ldg(&Bin[lane])      + xv.y * __ldg(&Bin[32 + lane])
              + xv.z * __ldg(&Bin[64 + lane]) + xv.w * __ldg(&Bin[96 + lane]);
    float e = __expf(acc);
    float ss = e;
#pragma unroll
    for (int o = 16; o; o >>= 1) ss += __shfl_xor_sync(0xffffffffu, ss, o);
    unsigned q = __float2uint_rn(fminf(e / ss * 255.0f, 255.0f));
    stg[wid][lane] = (unsigned char)q;
    __syncwarp();
    if (lane < 4) {
        uint2 v = *(uint2*)&stg[wid][lane * 8];
        ((uint2*)out)[n * 4 + lane] = v;
    }
}

// ---------------------------------------------------------------------------
// hidden conv layer, int8 storage, MLP-16 gather (proven best structure).
// R17 micro-opts: invS folded into shared weights at load; self-row load
// hoisted above the gather loop; softmax without max-subtraction (logits
// bounded: |acc| <= ~4 on layer 1, ~1e-5 scale afterwards).
__global__ void __launch_bounds__(256) conv_kernel(
    const unsigned char* __restrict__ Ein, unsigned char* __restrict__ Eout,
    const float* __restrict__ Wa, const float* __restrict__ Wb,
    const float* __restrict__ cs_in, float* __restrict__ cs_out,
    float in_off, float in_scale) {
    __shared__ __align__(16) float sWa[HID][HID];
    __shared__ __align__(16) float sWb[HID][HID];
    __shared__ __align__(16) float sred[8][HID];
    int tid = threadIdx.x;
    int lane = tid & 31, wid = tid >> 5;
    for (int i = tid; i < HID * HID; i += 256) {
        float inv = 1.0f / cs_in[i >> 5];   // row k = i/32; fold invS into weights
        ((float*)sWa)[i] = __ldg(&Wa[i]) * inv;
        ((float*)sWb)[i] = __ldg(&Wb[i]) * inv;
    }
    __syncthreads();

    int nid = lane >> 2;         // node slot within warp (0..7)
    int fl  = lane & 3;          // quarter-row: features fl*8 .. fl*8+7
    int nb  = lane & 28;         // node base lane

    float colacc[8];
#pragma unroll
    for (int i = 0; i < 8; ++i) colacc[i] = 0.0f;

    const uint2* E2 = (const uint2*)Ein;

    for (int q = blockIdx.x * 8 + wid; q < NGRP; q += gridDim.x * 8) {
        int n = q * 8 + nid;
        int beg = g_rowptr[n], end = g_rowptr[n + 1];
        int deg = end - beg;
        // self-row load hoisted: overlaps with the gather loop below
        uint2 vx = __ldg(&E2[n * 4 + fl]);
        int md = deg;
        md = max(md, __shfl_xor_sync(0xffffffffu, md, 4));
        md = max(md, __shfl_xor_sync(0xffffffffu, md, 8));
        md = max(md, __shfl_xor_sync(0xffffffffu, md, 16));

        unsigned sA = 0, sB = 0, sC = 0, sD = 0;   // u16-pair accumulators

        int ic[4];
#pragma unroll
        for (int t4 = 0; t4 < 4; ++t4) {
            int p = beg + t4 * 4 + fl;
            ic[t4] = (t4 * 4 < md && p < end) ? __ldg(&g_csr[p]) : 0;
        }
        for (int base = 0; base < md; base += 16) {
            int nc[4];
#pragma unroll
            for (int t4 = 0; t4 < 4; ++t4) {
                int p = beg + base + 16 + t4 * 4 + fl;
                nc[t4] = (base + 16 + t4 * 4 < md && p < end) ? __ldg(&g_csr[p]) : 0;
            }
            uint2 v[16];
#pragma unroll
            for (int j = 0; j < 16; ++j) {
                int s = __shfl_sync(0xffffffffu, ic[j >> 2], nb + (j & 3));
                bool act = (base + j < deg);
                v[j] = act ? __ldg(&E2[s * 4 + fl]) : make_uint2(0u, 0u);
            }
#pragma unroll
            for (int j = 0; j < 16; ++j) {
                sA += __byte_perm(v[j].x, 0, 0x4140);  // b0 | b1<<16
                sB += __byte_perm(v[j].x, 0, 0x4342);  // b2 | b3<<16
                sC += __byte_perm(v[j].y, 0, 0x4140);
                sD += __byte_perm(v[j].y, 0, 0x4342);
            }
#pragma unroll
            for (int t4 = 0; t4 < 4; ++t4) ic[t4] = nc[t4];
        }

        float qs[8];
        qs[0] = (float)(sA & 0xFFFF); qs[1] = (float)(sA >> 16);
        qs[2] = (float)(sB & 0xFFFF); qs[3] = (float)(sB >> 16);
        qs[4] = (float)(sC & 0xFFFF); qs[5] = (float)(sC >> 16);
        qs[6] = (float)(sD & 0xFFFF); qs[7] = (float)(sD >> 16);

        float degf = (float)deg;
        float sc = g_invdeg[n];
        float avg[8], xd[8];
        xd[0] = (float)(vx.x & 0xFF);         xd[1] = (float)((vx.x >> 8) & 0xFF);
        xd[2] = (float)((vx.x >> 16) & 0xFF); xd[3] = (float)(vx.x >> 24);
        xd[4] = (float)(vx.y & 0xFF);         xd[5] = (float)((vx.y >> 8) & 0xFF);
        xd[6] = (float)((vx.y >> 16) & 0xFF); xd[7] = (float)(vx.y >> 24);
#pragma unroll
        for (int i = 0; i < 8; ++i) {
            avg[i] = (degf * in_off + qs[i] * in_scale) * sc;  // invS in weights
            xd[i]  = in_off + xd[i] * in_scale;
        }

        float acc[8];
#pragma unroll
        for (int i = 0; i < 8; ++i) acc[i] = 0.0f;
#pragma unroll
        for (int c = 0; c < 4; ++c) {
            int src = nb + c;
#pragma unroll
            for (int j = 0; j < 8; ++j) {
                float a  = __shfl_sync(0xffffffffu, avg[j], src);
                float xv2 = __shfl_sync(0xffffffffu, xd[j],  src);
                int k = c * 8 + j;
                float4 wa0 = *(const float4*)&sWa[k][fl * 8];
                float4 wa1 = *(const float4*)&sWa[k][fl * 8 + 4];
                float4 wb0 = *(const float4*)&sWb[k][fl * 8];
                float4 wb1 = *(const float4*)&sWb[k][fl * 8 + 4];
                acc[0] = fmaf(a, wa0.x, acc[0]); acc[1] = fmaf(a, wa0.y, acc[1]);
                acc[2] = fmaf(a, wa0.z, acc[2]); acc[3] = fmaf(a, wa0.w, acc[3]);
                acc[4] = fmaf(a, wa1.x, acc[4]); acc[5] = fmaf(a, wa1.y, acc[5]);
                acc[6] = fmaf(a, wa1.z, acc[6]); acc[7] = fmaf(a, wa1.w, acc[7]);
                acc[0] = fmaf(xv2, wb0.x, acc[0]); acc[1] = fmaf(xv2, wb0.y, acc[1]);
                acc[2] = fmaf(xv2, wb0.z, acc[2]); acc[3] = fmaf(xv2, wb0.w, acc[3]);
                acc[4] = fmaf(xv2, wb1.x, acc[4]); acc[5] = fmaf(xv2, wb1.y, acc[5]);
                acc[6] = fmaf(xv2, wb1.z, acc[6]); acc[7] = fmaf(xv2, wb1.w, acc[7]);
            }
        }

        // inner softmax over node's 32 features (4 lanes x 8 comps), no max shift
        float e[8], ss = 0.0f;
#pragma unroll
        for (int i = 0; i < 8; ++i) { e[i] = __expf(acc[i]); ss += e[i]; }
        ss += __shfl_xor_sync(0xffffffffu, ss, 1);
        ss += __shfl_xor_sync(0xffffffffu, ss, 2);
        float r = 1.0f / ss;
        unsigned qv[8];
#pragma unroll
        for (int i = 0; i < 8; ++i) {
            float E = __expf(e[i] * r);                 // in (1, e]
            unsigned qi = __float2uint_rn(fminf((E - 1.0f) * KOUT, 255.0f));
            qv[i] = qi;
            colacc[i] += 1.0f + (float)qi * SCALE_HID;  // dequantized stored value
        }
        uint2 o;
        o.x = qv[0] | (qv[1] << 8) | (qv[2] << 16) | (qv[3] << 24);
        o.y = qv[4] | (qv[5] << 8) | (qv[6] << 16) | (qv[7] << 24);
        ((uint2*)Eout)[n * 4 + fl] = o;
    }

    // column-sum reduction across the 8 node slots (lanes with same fl)
#pragma unroll
    for (int o = 4; o <= 16; o <<= 1) {
#pragma unroll
        for (int i = 0; i < 8; ++i)
            colacc[i] += __shfl_xor_sync(0xffffffffu, colacc[i], o);
    }
    if (lane < 4) {
        float4 c0 = make_float4(colacc[0], colacc[1], colacc[2], colacc[3]);
        float4 c1 = make_float4(colacc[4], colacc[5], colacc[6], colacc[7]);
        *(float4*)&sred[wid][fl * 8]     = c0;
        *(float4*)&sred[wid][fl * 8 + 4] = c1;
    }
    __syncthreads();
    if (wid == 0) {
        float t = sred[0][lane];
#pragma unroll
        for (int i = 1; i < 8; ++i) t += sred[i][lane];
        atomicAdd(&cs_out[lane], t);
    }
}

// ---------------------------------------------------------------------------
// final z: 8 nodes/warp, 4 lanes/node, uint2 loads + register dot.
__global__ void __launch_bounds__(256) out_z_kernel(
    const unsigned char* __restrict__ E, const float* __restrict__ cs,
    const float* __restrict__ Wout, const float* __restrict__ bout) {
    int lane = threadIdx.x & 31, wid = threadIdx.x >> 5;
    int nid = lane >> 2;
    int fl  = lane & 3;
    float w8[8];
#pragma unroll
    for (int i = 0; i < 8; ++i)
        w8[i] = __ldg(&Wout[fl * 8 + i]) / cs[fl * 8 + i];
    float b = __ldg(bout);
    const uint2* E2 = (const uint2*)E;
    float acc = 0.0f;
    for (int q = blockIdx.x * 8 + wid; q < NGRP; q += gridDim.x * 8) {
        int n = q * 8 + nid;
        uint2 vx = __ldg(&E2[n * 4 + fl]);
        float v = 0.0f;
        v += (1.0f + (float)(vx.x & 0xFF)         * SCALE_HID) * w8[0];
        v += (1.0f + (float)((vx.x >> 8) & 0xFF)  * SCALE_HID) * w8[1];
        v += (1.0f + (float)((vx.x >> 16) & 0xFF) * SCALE_HID) * w8[2];
        v += (1.0f + (float)(vx.x >> 24)          * SCALE_HID) * w8[3];
        v += (1.0f + (float)(vx.y & 0xFF)         * SCALE_HID) * w8[4];
        v += (1.0f + (float)((vx.y >> 8) & 0xFF)  * SCALE_HID) * w8[5];
        v += (1.0f + (float)((vx.y >> 16) & 0xFF) * SCALE_HID) * w8[6];
        v += (1.0f + (float)(vx.y >> 24)          * SCALE_HID) * w8[7];
        v += __shfl_xor_sync(0xffffffffu, v, 1);
        v += __shfl_xor_sync(0xffffffffu, v, 2);
        float e = __expf(v + b);
        if (fl == 0) { g_zexp[n] = e; acc += e; }
    }
#pragma unroll
    for (int o = 16; o; o >>= 1) acc += __shfl_xor_sync(0xffffffffu, acc, o);
    __shared__ float sred[8];
    if (lane == 0) sred[wid] = acc;
    __syncthreads();
    if (threadIdx.x == 0) {
        float t = 0.0f;
#pragma unroll
        for (int i = 0; i < 8; ++i) t += sred[i];
        atomicAdd(g_S, t);
    }
}

__global__ void out_norm_kernel(float* __restrict__ out) {
    int i = blockIdx.x * blockDim.x + threadIdx.x;
    if (i < N_NODES) out[i] = g_zexp[i] / g_S[0];
}

// ---------------------------------------------------------------------------
extern "C" void kernel_launch(void* const* d_in, const int* in_sizes, int n_in,
                              void* d_out, int out_size) {
    const float* x     = (const float*)d_in[0];
    const void*  ei    = d_in[1];                    // [2, N_EDGES] int32 or int64
    const float* Ain   = (const float*)d_in[2];
    const float* Bin   = (const float*)d_in[3];
    const float* Aconv = (const float*)d_in[4];      // [16,32,32]
    const float* Bconv = (const float*)d_in[5];
    const float* Wout  = (const float*)d_in[6];
    const float* bout  = (const float*)d_in[7];
    float* out         = (float*)d_out;

    unsigned char *pA, *pB;
    float *pcs;
    cudaGetSymbolAddress((void**)&pA, g_qbufA);
    cudaGetSymbolAddress((void**)&pB, g_qbufB);
    cudaGetSymbolAddress((void**)&pcs, g_colsum);

    hist_kernel<<<(N_EDGES + 255) / 256, 256>>>(ei);
    scan_kernel<<<1, 1024>>>();
    fill_kernel<<<(N_EDGES + 255) / 256, 256>>>(ei);

    proj_kernel<<<(N_NODES + 7) / 8, 256>>>(x, Ain, Bin, pA);

    unsigned char* bi = pA;
    unsigned char* bo = pB;
    for (int l = 0; l < NCONV; ++l) {
        float in_off   = (l == 0) ? 0.0f : 1.0f;
        float in_scale = (l == 0) ? (1.0f / 255.0f) : SCALE_HID;
        conv_kernel<<<444, 256>>>(bi, bo,
                                  Aconv + l * HID * HID, Bconv + l * HID * HID,
                                  pcs + l * HID, pcs + (l + 1) * HID,
                                  in_off, in_scale);
        unsigned char* t = bi; bi = bo; bo = t;
    }

    out_z_kernel<<<444, 256>>>(bi, pcs + NCONV * HID, Wout, bout);
    out_norm_kernel<<<(N_NODES + 255) / 256, 256>>>(out);
}